// round 4
// baseline (speedup 1.0000x reference)
#include <cuda_runtime.h>
#include <cuda_fp16.h>
#include <cstdint>

// Problem constants (fixed by setup_inputs)
#define BATCH   8
#define HH      128
#define WW      128
#define CC      256
#define HID     64
#define NTOK    (HH*WW)          // 16384 tokens per batch
#define NP      1024
#define KKEEP   768
#define TOK_ALL (BATCH*NTOK)     // 131072
#define BM      256
#define NBLK    (TOK_ALL/BM)     // 512
#define THREADS 512

// Scratch (device globals — no allocation allowed)
__device__ float g_imp[TOK_ALL];
__device__ int   g_idx[BATCH*KKEEP];

// ---------------- SMEM layout (bytes) ----------------
// BH/BL: w1 hi/lo, 8x8-blocked fp16, 32KB each
// A: 2 stages x (AH 16KB + AL 16KB) = 64KB
#define OFF_BH  0
#define OFF_BL  32768
#define OFF_A   65536
#define OFF_B1  131072
#define OFF_W2  131328
#define SMEM_SZ 131584

// ---------------- asm helpers ----------------
static __device__ __forceinline__ uint32_t smem_u32(const void* p) {
    uint32_t a;
    asm("{ .reg .u64 t; cvta.to.shared.u64 t, %1; cvt.u32.u64 %0, t; }" : "=r"(a) : "l"(p));
    return a;
}
static __device__ __forceinline__ uint32_t h2u(__half2 h) {
    return *reinterpret_cast<uint32_t*>(&h);
}
#define LDSM_X4(r, a) \
    asm volatile("ldmatrix.sync.aligned.m8n8.x4.shared.b16 {%0,%1,%2,%3}, [%4];" \
        : "=r"((r)[0]), "=r"((r)[1]), "=r"((r)[2]), "=r"((r)[3]) : "r"(a))
#define LDSM_X4T(r, a) \
    asm volatile("ldmatrix.sync.aligned.m8n8.x4.trans.shared.b16 {%0,%1,%2,%3}, [%4];" \
        : "=r"((r)[0]), "=r"((r)[1]), "=r"((r)[2]), "=r"((r)[3]) : "r"(a))
#define MMA16816(d, a, b) \
    asm volatile("mma.sync.aligned.m16n8k16.row.col.f32.f16.f16.f32 " \
        "{%0,%1,%2,%3}, {%4,%5,%6,%7}, {%8,%9}, {%0,%1,%2,%3};" \
        : "+f"((d)[0]), "+f"((d)[1]), "+f"((d)[2]), "+f"((d)[3]) \
        : "r"((a)[0]), "r"((a)[1]), "r"((a)[2]), "r"((a)[3]), "r"((b)[0]), "r"((b)[1]))
#define STS64(a, r0, r1) \
    asm volatile("st.shared.v2.b32 [%0], {%1,%2};" :: "r"(a), "r"(r0), "r"(r1) : "memory")

static __device__ __forceinline__ float gelu_exact(float v) {
    return 0.5f * v * (1.0f + erff(v * 0.7071067811865476f));
}

// split-store one float4 as hi/lo half2 pairs
static __device__ __forceinline__ void split_store(uint32_t addr, float4 v) {
    __half2 h0 = __floats2half2_rn(v.x, v.y);
    __half2 h1 = __floats2half2_rn(v.z, v.w);
    __half2 l0 = __floats2half2_rn(v.x - __low2float(h0), v.y - __high2float(h0));
    __half2 l1 = __floats2half2_rn(v.z - __low2float(h1), v.w - __high2float(h1));
    STS64(addr,         h2u(h0), h2u(h1));
    STS64(addr + 16384, h2u(l0), h2u(l1));
}

// ============ Kernel A: fp16-split HMMA MLP -> per-token importance ============
__global__ __launch_bounds__(THREADS, 1) void score_mma(
    const float* __restrict__ tokens,
    const float* __restrict__ w1,
    const float* __restrict__ b1,
    const float* __restrict__ w2,
    const float* __restrict__ b2)
{
    extern __shared__ char sm[];
    const uint32_t sb = smem_u32(sm);
    const int tid = threadIdx.x;
    const int lane = tid & 31, wid = tid >> 5;
    const int g = lane >> 2, tig = lane & 3;
    const int m0 = blockIdx.x * BM;

    if (tid < 64) {
        ((float*)(sm + OFF_B1))[tid] = b1[tid];
        ((float*)(sm + OFF_W2))[tid] = w2[tid];
    }
    const float b2v = b2[0];

    // stage w1 hi/lo into 8x8-blocked fp16 tiles
#pragma unroll
    for (int j = 0; j < 16; ++j) {
        int pi = tid + j * THREADS;
        int k = pi >> 5, n = (pi & 31) * 2;
        float2 v = *(const float2*)(w1 + k * HID + n);
        __half2 h = __floats2half2_rn(v.x, v.y);
        __half2 l = __floats2half2_rn(v.x - __low2float(h), v.y - __high2float(h));
        uint32_t off = (uint32_t)(((k >> 3) * 8 + (n >> 3)) * 128 + (k & 7) * 16 + (n & 7) * 2);
        *(uint32_t*)(sm + OFF_BH + off) = h2u(h);
        *(uint32_t*)(sm + OFF_BL + off) = h2u(l);
    }

    const int row0 = tid >> 3;
    const int col4 = tid & 7;
    const float4* ap = (const float4*)(tokens + (size_t)(m0 + row0) * CC) + col4;
    const uint32_t sa0 = (uint32_t)(((row0 >> 3) * 4 + (col4 >> 1)) * 128
                                    + (row0 & 7) * 16 + (col4 & 1) * 8);

    float4 pf[4];
#pragma unroll
    for (int p = 0; p < 4; ++p) pf[p] = ap[p * 4096];          // chunk 0
#pragma unroll
    for (int p = 0; p < 4; ++p)
        split_store(sb + OFF_A + sa0 + p * 4096, pf[p]);       // -> stage 0
#pragma unroll
    for (int p = 0; p < 4; ++p) pf[p] = ap[p * 4096 + 8];      // chunk 1
    __syncthreads();

    float acc[8][4];
#pragma unroll
    for (int nt = 0; nt < 8; ++nt)
#pragma unroll
        for (int q = 0; q < 4; ++q) acc[nt][q] = 0.0f;

    const uint32_t a_tile = (uint32_t)((wid * 2 + ((lane >> 3) & 1)) * 4 + (lane >> 4));
    const uint32_t a_lane = (uint32_t)((lane & 7) * 16);
    const uint32_t b_base = sb + OFF_BH + (uint32_t)(lane >> 4) * 32768
                          + (uint32_t)(((lane >> 3) & 1) * 8 * 128) + a_lane;

    for (int c = 0; c < 8; ++c) {
        const int s = c & 1;
        if (c < 7) {
            const uint32_t st_b = sb + OFF_A + (s ^ 1) * 32768 + sa0;
#pragma unroll
            for (int p = 0; p < 4; ++p) split_store(st_b + p * 4096, pf[p]);
        }
        if (c < 6) {
#pragma unroll
            for (int p = 0; p < 4; ++p) pf[p] = ap[p * 4096 + (c + 2) * 8];
        }

        const uint32_t abase = sb + OFF_A + s * 32768;
#pragma unroll
        for (int step = 0; step < 2; ++step) {
            uint32_t ah[4], al[4];
            uint32_t aadr = abase + (a_tile + step * 2) * 128 + a_lane;
            LDSM_X4(ah, aadr);
            LDSM_X4(al, aadr + 16384);
            const int ktg = c * 4 + step * 2;
#pragma unroll
            for (int nt = 0; nt < 8; ++nt) {
                uint32_t b4[4];
                LDSM_X4T(b4, b_base + (uint32_t)((ktg * 8 + nt) * 128));
                MMA16816(acc[nt], ah, b4);
                MMA16816(acc[nt], ah, b4 + 2);
                MMA16816(acc[nt], al, b4);
            }
        }
        __syncthreads();
    }

    const float* b1s = (const float*)(sm + OFF_B1);
    const float* w2s = (const float*)(sm + OFF_W2);
    float p0 = 0.0f, p1 = 0.0f;
#pragma unroll
    for (int nt = 0; nt < 8; ++nt) {
        int c0 = nt * 8 + tig * 2, c1 = c0 + 1;
        float bb0 = b1s[c0], bb1 = b1s[c1];
        float ww0 = w2s[c0], ww1 = w2s[c1];
        p0 += gelu_exact(acc[nt][0] + bb0) * ww0 + gelu_exact(acc[nt][1] + bb1) * ww1;
        p1 += gelu_exact(acc[nt][2] + bb0) * ww0 + gelu_exact(acc[nt][3] + bb1) * ww1;
    }
    p0 += __shfl_xor_sync(0xffffffffu, p0, 1);
    p0 += __shfl_xor_sync(0xffffffffu, p0, 2);
    p1 += __shfl_xor_sync(0xffffffffu, p1, 1);
    p1 += __shfl_xor_sync(0xffffffffu, p1, 2);
    if (tig == 0) {
        int r0 = m0 + wid * 16 + g;
        g_imp[r0]     = 1.0f / (1.0f + expf(-(p0 + b2v)));
        g_imp[r0 + 8] = 1.0f / (1.0f + expf(-(p1 + b2v)));
    }
}

// ============ Kernel B: patch scores + stable top-768 ============
__global__ __launch_bounds__(1024) void select_kernel()
{
    const int b = blockIdx.x;
    const int p = threadIdx.x;
    __shared__ float s[NP];
    __shared__ int   woff[32];

    const int pr = p >> 5, pc = p & 31;
    const float* base = g_imp + b * NTOK;
    float sum = 0.0f;
#pragma unroll
    for (int i = 0; i < 4; i++) {
        float4 v = *(const float4*)(base + (pr * 4 + i) * WW + pc * 4);
        sum += (v.x + v.y) + (v.z + v.w);
    }
    s[p] = sum;
    __syncthreads();

    const float sp = sum;
    int rank = 0;
    const float4* s4 = (const float4*)s;
#pragma unroll 4
    for (int j4 = 0; j4 < NP / 4; j4++) {
        float4 v = s4[j4];
        int j = j4 * 4;
        rank += (int)((v.x > sp) || (v.x == sp && (j + 0) < p));
        rank += (int)((v.y > sp) || (v.y == sp && (j + 1) < p));
        rank += (int)((v.z > sp) || (v.z == sp && (j + 2) < p));
        rank += (int)((v.w > sp) || (v.w == sp && (j + 3) < p));
    }
    const bool kept = (rank < KKEEP);

    const unsigned mask = __ballot_sync(0xffffffffu, kept);
    const int lane = p & 31, warp = p >> 5;
    const int lpre = __popc(mask & ((1u << lane) - 1u));
    if (lane == 0) woff[warp] = __popc(mask);
    __syncthreads();
    if (p < 32) {
        int v = woff[p];
        int inc = v;
        for (int d = 1; d < 32; d <<= 1) {
            int t = __shfl_up_sync(0xffffffffu, inc, d);
            if (lane >= d) inc += t;
        }
        woff[p] = inc - v;
    }
    __syncthreads();
    if (kept)
        g_idx[b * KKEEP + woff[warp] + lpre] = p;
}

// ============ Kernel C: gather + spatial reassembly ============
__global__ __launch_bounds__(128) void gather_kernel(
    const float* __restrict__ tokens, float* __restrict__ out)
{
    const int k = blockIdx.x;
    const int b = blockIdx.y;
    const int p = g_idx[b * KKEEP + k];
    const int pr = p >> 5, pc = p & 31;
    const int kr = k >> 5, kc = k & 31;

    const float4* src = (const float4*)(tokens + (size_t)b * NTOK * CC);
    float4*       dst = (float4*)(out + (size_t)b * (KKEEP * 16) * CC);
    const int t = threadIdx.x;

#pragma unroll
    for (int i = 0; i < 4; i++) {
        size_t so   = (size_t)((pr * 4 + i) * WW + pc * 4) * (CC / 4);
        size_t dofs = (size_t)((kr * 4 + i) * WW + kc * 4) * (CC / 4);
#pragma unroll
        for (int it = 0; it < 2; it++) {
            int e = it * 128 + t;
            dst[dofs + e] = src[so + e];
        }
    }
}

// ============================ launch ============================
extern "C" void kernel_launch(void* const* d_in, const int* in_sizes, int n_in,
                              void* d_out, int out_size)
{
    const float* tokens = (const float*)d_in[0];
    const float* w1 = (const float*)d_in[1];
    const float* b1 = (const float*)d_in[2];
    const float* w2 = (const float*)d_in[3];
    const float* b2 = (const float*)d_in[4];
    (void)in_sizes; (void)n_in; (void)out_size;

    cudaFuncSetAttribute(score_mma, cudaFuncAttributeMaxDynamicSharedMemorySize, SMEM_SZ);
    score_mma<<<NBLK, THREADS, SMEM_SZ>>>(tokens, w1, b1, w2, b2);
    select_kernel<<<BATCH, 1024>>>();
    gather_kernel<<<dim3(KKEEP, BATCH), 128>>>(tokens, (float*)d_out);
}